// round 4
// baseline (speedup 1.0000x reference)
#include <cuda_runtime.h>
#include <cuda_bf16.h>
#include <cstdint>

// ===========================================================================
// MHA B=2,S=2048,E=1024,H=16,D=64 fp32.
//  - 4 GEMMs via mma.sync.m16n8k16 bf16 with hi/lo split (3 MMAs, fp32 acc)
//    (tcgen05 is NOT available: harness PTX target is plain sm_103)
//  - flash attention SIMT f32x2, group-wise online softmax (no spills)
// ===========================================================================

typedef unsigned long long ull;
#define DI __device__ __forceinline__

DI ull pk2(float lo, float hi) {
    ull r; asm("mov.b64 %0, {%1,%2};" : "=l"(r) : "f"(lo), "f"(hi)); return r;
}
DI void upk2(ull v, float& lo, float& hi) {
    asm("mov.b64 {%0,%1}, %2;" : "=f"(lo), "=f"(hi) : "l"(v));
}
DI ull ffma2(ull a, ull b, ull c) {
    ull d; asm("fma.rn.f32x2 %0, %1, %2, %3;" : "=l"(d) : "l"(a), "l"(b), "l"(c)); return d;
}
DI ull fmul2(ull a, ull b) {
    ull d; asm("mul.rn.f32x2 %0, %1, %2;" : "=l"(d) : "l"(a), "l"(b)); return d;
}
DI uint32_t smem_u32(const void* p) {
    uint32_t a;
    asm("{ .reg .u64 t; cvta.to.shared.u64 t, %1; cvt.u32.u64 %0, t; }" : "=r"(a) : "l"(p));
    return a;
}

DI void cp_async16(uint32_t saddr, const void* gaddr) {
    asm volatile("cp.async.cg.shared.global [%0], [%1], 16;"
                 :: "r"(saddr), "l"(gaddr) : "memory");
}
DI void cp_commit() { asm volatile("cp.async.commit_group;" ::: "memory"); }
DI void cp_wait1()  { asm volatile("cp.async.wait_group 1;" ::: "memory"); }
DI void cp_wait0()  { asm volatile("cp.async.wait_group 0;" ::: "memory"); }

DI void ldm_x4(uint32_t& r0, uint32_t& r1, uint32_t& r2, uint32_t& r3, uint32_t a) {
    asm volatile("ldmatrix.sync.aligned.m8n8.x4.shared.b16 {%0,%1,%2,%3}, [%4];"
                 : "=r"(r0), "=r"(r1), "=r"(r2), "=r"(r3) : "r"(a));
}
DI void mma16816(float* c, const uint32_t* a, const uint32_t* b) {
    asm volatile(
        "mma.sync.aligned.m16n8k16.row.col.f32.bf16.bf16.f32 "
        "{%0,%1,%2,%3}, {%4,%5,%6,%7}, {%8,%9}, {%0,%1,%2,%3};"
        : "+f"(c[0]), "+f"(c[1]), "+f"(c[2]), "+f"(c[3])
        : "r"(a[0]), "r"(a[1]), "r"(a[2]), "r"(a[3]), "r"(b[0]), "r"(b[1]));
}

constexpr int B = 2, S = 2048, E = 1024, H = 16, D = 64;

// scratch (__device__ globals per allocation rules)
__device__ float g_q[B * H * S * D];
__device__ float g_k[B * H * S * D];
__device__ float g_v[B * H * S * D];
__device__ float g_att[B * S * E];
__device__ __nv_bfloat16 g_xhi[4096 * 1024];
__device__ __nv_bfloat16 g_xlo[4096 * 1024];
__device__ __nv_bfloat16 g_whi[1024 * 1024];
__device__ __nv_bfloat16 g_wlo[1024 * 1024];

// ---------------------------------------------------------------------------
// fp32 -> (bf16 hi, bf16 lo) split
// ---------------------------------------------------------------------------
__global__ __launch_bounds__(256) void cvt_kernel(const float* __restrict__ x,
                                                  __nv_bfloat16* __restrict__ hi,
                                                  __nv_bfloat16* __restrict__ lo, int n4)
{
    int i = blockIdx.x * 256 + threadIdx.x;
    if (i >= n4) return;
    float4 v = ((const float4*)x)[i];
    __nv_bfloat16 h0 = __float2bfloat16(v.x), h1 = __float2bfloat16(v.y);
    __nv_bfloat16 h2 = __float2bfloat16(v.z), h3 = __float2bfloat16(v.w);
    __nv_bfloat16 l0 = __float2bfloat16(v.x - __bfloat162float(h0));
    __nv_bfloat16 l1 = __float2bfloat16(v.y - __bfloat162float(h1));
    __nv_bfloat16 l2 = __float2bfloat16(v.z - __bfloat162float(h2));
    __nv_bfloat16 l3 = __float2bfloat16(v.w - __bfloat162float(h3));
    ((__nv_bfloat162*)hi)[2 * i]     = __nv_bfloat162(h0, h1);
    ((__nv_bfloat162*)hi)[2 * i + 1] = __nv_bfloat162(h2, h3);
    ((__nv_bfloat162*)lo)[2 * i]     = __nv_bfloat162(l0, l1);
    ((__nv_bfloat162*)lo)[2 * i + 1] = __nv_bfloat162(l2, l3);
}

// ---------------------------------------------------------------------------
// mma.sync GEMM: C[4096,1024] = X @ W^T + bias (both operands k-major)
// CTA 128x128, BK=32, 8 warps in 2x4 grid, warp tile 64x32.
// smem rows padded to 40 bf16 (80B) -> conflict-free ldmatrix.
// 3-MMA bf16 hi/lo emulation of fp32.
// MODE 0: scatter to [B,H,S,D];  MODE 1: row-major.
// ---------------------------------------------------------------------------
constexpr int PAD = 40;                       // bf16 elems per smem row
constexpr int MAT_BYTES = 128 * PAD * 2;      // 10240
constexpr int STAGE_BYTES = 4 * MAT_BYTES;    // 40960 (Ahi,Alo,Bhi,Blo)
constexpr int GEMM_SMEM = 2 * STAGE_BYTES;    // 81920

template <int MODE>
__global__ __launch_bounds__(256) void gemm_tc(const __nv_bfloat16* __restrict__ Xhi,
                                               const __nv_bfloat16* __restrict__ Xlo,
                                               const __nv_bfloat16* __restrict__ Whi,
                                               const __nv_bfloat16* __restrict__ Wlo,
                                               const float* __restrict__ bias,
                                               float* __restrict__ out)
{
    extern __shared__ char smem[];
    const uint32_t sb = smem_u32(smem);
    const int tid = threadIdx.x;
    const int wid = tid >> 5, lane = tid & 31;
    const int warp_m = wid >> 2, warp_n = wid & 3;  // 2 x 4
    const int m0 = blockIdx.y * 128, n0 = blockIdx.x * 128;

    const __nv_bfloat16* gsrc[4] = { Xhi + (size_t)m0 * 1024, Xlo + (size_t)m0 * 1024,
                                     Whi + (size_t)n0 * 1024, Wlo + (size_t)n0 * 1024 };

    // issue one chunk's cp.async (8x 16B per thread)
    auto issue = [&](int c, int buf) {
        const int k0 = c * 32;
        const uint32_t stb = sb + buf * STAGE_BYTES;
#pragma unroll
        for (int mat = 0; mat < 4; mat++) {
#pragma unroll
            for (int i = 0; i < 2; i++) {
                int seg = i * 256 + tid;            // 0..511
                int row = seg >> 2, sg = seg & 3;   // 4 x 16B per 64B row
                const void* g = gsrc[mat] + (size_t)row * 1024 + k0 + sg * 8;
                uint32_t sa = stb + mat * MAT_BYTES + (row * PAD + sg * 8) * 2;
                cp_async16(sa, g);
            }
        }
        cp_commit();
    };

    float acc[4][4][4];
#pragma unroll
    for (int i = 0; i < 4; i++)
#pragma unroll
        for (int j = 0; j < 4; j++)
#pragma unroll
            for (int r = 0; r < 4; r++) acc[i][j][r] = 0.0f;

    // ldmatrix per-thread base offsets (bytes)
    const uint32_t a_off = (((warp_m * 64 + (lane & 15)) * PAD + (lane >> 4) * 8) * 2);
    const uint32_t b_off = (((warp_n * 32 + ((lane >> 4) & 1) * 8 + (lane & 7)) * PAD
                             + ((lane >> 3) & 1) * 8) * 2);

    issue(0, 0);
    issue(1, 1);

    for (int c = 0; c < 32; c++) {
        if (c < 31) cp_wait1(); else cp_wait0();
        __syncthreads();

        const uint32_t stb = sb + (c & 1) * STAGE_BYTES;
        const uint32_t Ah = stb, Al = stb + MAT_BYTES;
        const uint32_t Bh = stb + 2 * MAT_BYTES, Bl = stb + 3 * MAT_BYTES;

#pragma unroll
        for (int ks = 0; ks < 2; ks++) {
            const uint32_t kb = ks * 16 * 2;
            uint32_t ah[4][4], al[4][4], bh[4][2], bl[4][2];
#pragma unroll
            for (int mi = 0; mi < 4; mi++) {
                uint32_t o = a_off + mi * (16 * PAD * 2) + kb;
                ldm_x4(ah[mi][0], ah[mi][1], ah[mi][2], ah[mi][3], Ah + o);
                ldm_x4(al[mi][0], al[mi][1], al[mi][2], al[mi][3], Al + o);
            }
#pragma unroll
            for (int p = 0; p < 2; p++) {
                uint32_t o = b_off + p * (16 * PAD * 2) + kb;
                ldm_x4(bh[2 * p][0], bh[2 * p][1], bh[2 * p + 1][0], bh[2 * p + 1][1], Bh + o);
                ldm_x4(bl[2 * p][0], bl[2 * p][1], bl[2 * p + 1][0], bl[2 * p + 1][1], Bl + o);
            }
#pragma unroll
            for (int mi = 0; mi < 4; mi++)
#pragma unroll
                for (int ni = 0; ni < 4; ni++) {
                    mma16816(acc[mi][ni], ah[mi], bh[ni]);
                    mma16816(acc[mi][ni], ah[mi], bl[ni]);
                    mma16816(acc[mi][ni], al[mi], bh[ni]);
                }
        }
        __syncthreads();
        if (c + 2 < 32) issue(c + 2, c & 1);
    }

    // epilogue
#pragma unroll
    for (int mi = 0; mi < 4; mi++) {
#pragma unroll
        for (int ni = 0; ni < 4; ni++) {
            int row = m0 + warp_m * 64 + mi * 16 + (lane >> 2);
            int col = n0 + warp_n * 32 + ni * 8 + (lane & 3) * 2;
            float2 bv = *(const float2*)&bias[col];
#pragma unroll
            for (int h2 = 0; h2 < 2; h2++) {
                int r = row + h2 * 8;
                float2 v;
                v.x = acc[mi][ni][h2 * 2 + 0] + bv.x;
                v.y = acc[mi][ni][h2 * 2 + 1] + bv.y;
                if (MODE == 0) {
                    int bb = r >> 11, ss = r & 2047;
                    int hh = col >> 6, dd = col & 63;
                    *(float2*)&out[((size_t)(bb * H + hh) * S + ss) * D + dd] = v;
                } else {
                    *(float2*)&out[(size_t)r * 1024 + col] = v;
                }
            }
        }
    }
}

// ---------------------------------------------------------------------------
// flash attention, SIMT f32x2, group-wise online softmax (16 keys/group).
// One thread per Q row; K tile transposed [d][68]; Q stride 65 (conflict-free).
// ---------------------------------------------------------------------------
constexpr int BQ = 128, TK = 64;
constexpr int QSTR = 65, KSTR = 68;
constexpr int ATTN_SMEM = (BQ * QSTR + D * KSTR + TK * D) * 4;  // 67072

__global__ __launch_bounds__(128) void attn_kernel(const float* __restrict__ Q,
                                                   const float* __restrict__ K,
                                                   const float* __restrict__ V,
                                                   float* __restrict__ Oout)
{
    extern __shared__ float sm[];
    float* Qs  = sm;                  // [128][65]
    float* Kst = sm + BQ * QSTR;      // [64 d][68 keys]
    float* Vs  = Kst + D * KSTR;      // [64 keys][64 d]

    const int t  = threadIdx.x;
    const int bh = blockIdx.y;
    const int q0 = blockIdx.x * BQ;
    const float* Qb = Q + (size_t)bh * (S * D);
    const float* Kb = K + (size_t)bh * (S * D);
    const float* Vb = V + (size_t)bh * (S * D);

#pragma unroll
    for (int i = 0; i < BQ * D / 128; i++) {
        int idx = i * 128 + t;
        int r = idx >> 6, d = idx & 63;
        Qs[r * QSTR + d] = Qb[(q0 + r) * D + d] * 0.125f;
    }

    ull o2[32];
#pragma unroll
    for (int i = 0; i < 32; i++) o2[i] = 0ull;
    float m_run = -3.0e38f, l_run = 0.0f;

    for (int kt = 0; kt < S; kt += TK) {
        __syncthreads();
#pragma unroll
        for (int i = 0; i < TK * D / 128; i++) {
            int idx = i * 128 + t;
            int j = idx >> 6, d = idx & 63;
            Kst[d * KSTR + j] = Kb[(kt + j) * D + d];
            Vs[j * D + d]     = Vb[(kt + j) * D + d];
        }
        __syncthreads();

#pragma unroll
        for (int g = 0; g < 4; g++) {
            ull s2[8];
#pragma unroll
            for (int i = 0; i < 8; i++) s2[i] = 0ull;

#pragma unroll
            for (int dc = 0; dc < D; dc += 16) {
                float qf[16];
#pragma unroll
                for (int u = 0; u < 16; u++) qf[u] = Qs[t * QSTR + dc + u];
#pragma unroll
                for (int dd = 0; dd < 16; dd++) {
                    ull q2 = pk2(qf[dd], qf[dd]);
                    const ulonglong2* kr = (const ulonglong2*)&Kst[(dc + dd) * KSTR];
#pragma unroll
                    for (int u = 0; u < 4; u++) {
                        ulonglong2 kv = kr[g * 4 + u];
                        s2[2 * u]     = ffma2(q2, kv.x, s2[2 * u]);
                        s2[2 * u + 1] = ffma2(q2, kv.y, s2[2 * u + 1]);
                    }
                }
            }

            float gmax = -3.0e38f;
#pragma unroll
            for (int i = 0; i < 8; i++) {
                float a, b2; upk2(s2[i], a, b2);
                gmax = fmaxf(gmax, fmaxf(a, b2));
            }
            if (__any_sync(0xffffffffu, gmax > m_run)) {
                float mnew = fmaxf(m_run, gmax);
                float alpha = __expf(m_run - mnew);
                l_run *= alpha;
                ull al2 = pk2(alpha, alpha);
#pragma unroll
                for (int i = 0; i < 32; i++) o2[i] = fmul2(o2[i], al2);
                m_run = mnew;
            }
            float lsum = 0.0f;
#pragma unroll
            for (int i = 0; i < 8; i++) {
                float a, b2; upk2(s2[i], a, b2);
                float p0 = __expf(a - m_run);
                float p1 = __expf(b2 - m_run);
                lsum += p0 + p1;
                s2[i] = pk2(p0, p1);
            }
            l_run += lsum;

#pragma unroll
            for (int j2 = 0; j2 < 8; j2++) {
                int j = g * 16 + 2 * j2;
                float p0, p1; upk2(s2[j2], p0, p1);
                ull pa = pk2(p0, p0), pb = pk2(p1, p1);
                const ulonglong2* v0 = (const ulonglong2*)&Vs[j * D];
                const ulonglong2* v1 = (const ulonglong2*)&Vs[(j + 1) * D];
#pragma unroll
                for (int cp = 0; cp < 16; cp++) {
                    ulonglong2 va = v0[cp];
                    ulonglong2 vb = v1[cp];
                    o2[2 * cp]     = ffma2(pa, va.x, o2[2 * cp]);
                    o2[2 * cp + 1] = ffma2(pa, va.y, o2[2 * cp + 1]);
                    o2[2 * cp]     = ffma2(pb, vb.x, o2[2 * cp]);
                    o2[2 * cp + 1] = ffma2(pb, vb.y, o2[2 * cp + 1]);
                }
            }
        }
    }

    float inv_l = 1.0f / l_run;
    int bb = bh >> 4, hh = bh & 15;
    float* dst = Oout + (size_t)(bb * S + q0 + t) * E + hh * D;
#pragma unroll
    for (int cp = 0; cp < 16; cp++) {
        float x0, x1, x2, x3;
        upk2(o2[2 * cp], x0, x1);
        upk2(o2[2 * cp + 1], x2, x3);
        float4 o4 = { x0 * inv_l, x1 * inv_l, x2 * inv_l, x3 * inv_l };
        *(float4*)&dst[cp * 4] = o4;
    }
}

// ---------------------------------------------------------------------------
extern "C" void kernel_launch(void* const* d_in, const int* in_sizes, int n_in,
                              void* d_out, int out_size)
{
    const float* query = (const float*)d_in[0];
    const float* key   = (const float*)d_in[1];
    const float* value = (const float*)d_in[2];
    const float* Wq    = (const float*)d_in[3];
    const float* bq    = (const float*)d_in[4];
    const float* Wk    = (const float*)d_in[5];
    const float* bk    = (const float*)d_in[6];
    const float* Wv    = (const float*)d_in[7];
    const float* bv    = (const float*)d_in[8];
    const float* Wo    = (const float*)d_in[9];
    const float* bo    = (const float*)d_in[10];

    void *pq, *pk, *pv, *patt, *pxh, *pxl, *pwh, *pwl;
    cudaGetSymbolAddress(&pq, g_q);
    cudaGetSymbolAddress(&pk, g_k);
    cudaGetSymbolAddress(&pv, g_v);
    cudaGetSymbolAddress(&patt, g_att);
    cudaGetSymbolAddress(&pxh, g_xhi);
    cudaGetSymbolAddress(&pxl, g_xlo);
    cudaGetSymbolAddress(&pwh, g_whi);
    cudaGetSymbolAddress(&pwl, g_wlo);

    __nv_bfloat16* xhi = (__nv_bfloat16*)pxh;
    __nv_bfloat16* xlo = (__nv_bfloat16*)pxl;
    __nv_bfloat16* whi = (__nv_bfloat16*)pwh;
    __nv_bfloat16* wlo = (__nv_bfloat16*)pwl;

    cudaFuncSetAttribute(gemm_tc<0>, cudaFuncAttributeMaxDynamicSharedMemorySize, GEMM_SMEM);
    cudaFuncSetAttribute(gemm_tc<1>, cudaFuncAttributeMaxDynamicSharedMemorySize, GEMM_SMEM);
    cudaFuncSetAttribute(attn_kernel, cudaFuncAttributeMaxDynamicSharedMemorySize, ATTN_SMEM);

    const int NX4 = 4096 * 1024 / 4, NW4 = 1024 * 1024 / 4;
    dim3 ggrid(8, 32);

    const float* xs[3] = { query, key, value };
    const float* ws[3] = { Wq, Wk, Wv };
    const float* bs[3] = { bq, bk, bv };
    float* outs[3] = { (float*)pq, (float*)pk, (float*)pv };

    for (int p = 0; p < 3; p++) {
        cvt_kernel<<<(NX4 + 255) / 256, 256>>>(xs[p], xhi, xlo, NX4);
        cvt_kernel<<<(NW4 + 255) / 256, 256>>>(ws[p], whi, wlo, NW4);
        gemm_tc<0><<<ggrid, 256, GEMM_SMEM>>>(xhi, xlo, whi, wlo, bs[p], outs[p]);
    }

    dim3 agrid(S / BQ, B * H);
    attn_kernel<<<agrid, 128, ATTN_SMEM>>>((const float*)pq, (const float*)pk,
                                           (const float*)pv, (float*)patt);

    cvt_kernel<<<(NX4 + 255) / 256, 256>>>((const float*)patt, xhi, xlo, NX4);
    cvt_kernel<<<(NW4 + 255) / 256, 256>>>(Wo, whi, wlo, NW4);
    gemm_tc<1><<<ggrid, 256, GEMM_SMEM>>>(xhi, xlo, whi, wlo, bo, (float*)d_out);
}

// round 5
// speedup vs baseline: 1.3110x; 1.3110x over previous
#include <cuda_runtime.h>
#include <cstdint>

// ===========================================================================
// MHA B=2,S=2048,E=1024,H=16,D=64 fp32.
//  - GEMMs: SIMT f32x2 (fma.rn.f32x2), 128x128 tile, BK=8 (measured engine)
//    * 3 projections fused into ONE launch via blockIdx.z
//  - flash attention SIMT f32x2, group-wise online softmax (no spills)
//  (tcgen05 unusable: harness PTX target is plain sm_103; mma.sync HMMA
//   measured ~FFMA-class on this chip -> SIMT f32x2 is the best pipe.)
// ===========================================================================

typedef unsigned long long ull;
#define DI __device__ __forceinline__

DI ull pk2(float lo, float hi) {
    ull r; asm("mov.b64 %0, {%1,%2};" : "=l"(r) : "f"(lo), "f"(hi)); return r;
}
DI void upk2(ull v, float& lo, float& hi) {
    asm("mov.b64 {%0,%1}, %2;" : "=f"(lo), "=f"(hi) : "l"(v));
}
DI ull ffma2(ull a, ull b, ull c) {
    ull d; asm("fma.rn.f32x2 %0, %1, %2, %3;" : "=l"(d) : "l"(a), "l"(b), "l"(c)); return d;
}
DI ull fmul2(ull a, ull b) {
    ull d; asm("mul.rn.f32x2 %0, %1, %2;" : "=l"(d) : "l"(a), "l"(b)); return d;
}

constexpr int B = 2, S = 2048, E = 1024, H = 16, D = 64;

// scratch (__device__ globals per allocation rules)
__device__ float g_q[B * H * S * D];
__device__ float g_k[B * H * S * D];
__device__ float g_v[B * H * S * D];
__device__ float g_att[B * S * E];

// ---------------------------------------------------------------------------
// SIMT f32x2 GEMM body: C[m,n] = sum_k X[m,k]*W[n,k] + bias[n]
// 128x128 tile, BK=8, 256 threads, 8x8 per thread.
// MODE 0: scatter cols n=(h,d) into [B,H,S,D];  MODE 1: row-major.
// ---------------------------------------------------------------------------
template <int MODE>
DI void gemm_body(const float* __restrict__ X, const float* __restrict__ W,
                  const float* __restrict__ bias, float* __restrict__ out)
{
    __shared__ float As[8][132];
    __shared__ float Ws[8][132];

    const int tid = threadIdx.x;
    const int tx = tid & 15, ty = tid >> 4;
    const int m0 = blockIdx.y * 128;
    const int n0 = blockIdx.x * 128;
    const int lr = tid >> 1;        // 0..127
    const int lc = (tid & 1) << 2;  // 0 or 4

    const float* Xp = X + (size_t)(m0 + lr) * 1024 + lc;
    const float* Wp = W + (size_t)(n0 + lr) * 1024 + lc;

    ull acc[8][4];
#pragma unroll
    for (int i = 0; i < 8; i++)
#pragma unroll
        for (int j = 0; j < 4; j++) acc[i][j] = 0ull;

    float4 av = *(const float4*)Xp;
    float4 wv = *(const float4*)Wp;

    for (int k0 = 0; k0 < 1024; k0 += 8) {
        __syncthreads();
        As[lc + 0][lr] = av.x; As[lc + 1][lr] = av.y;
        As[lc + 2][lr] = av.z; As[lc + 3][lr] = av.w;
        Ws[lc + 0][lr] = wv.x; Ws[lc + 1][lr] = wv.y;
        Ws[lc + 2][lr] = wv.z; Ws[lc + 3][lr] = wv.w;
        __syncthreads();
        if (k0 + 8 < 1024) {
            av = *(const float4*)(Xp + k0 + 8);
            wv = *(const float4*)(Wp + k0 + 8);
        }
#pragma unroll
        for (int kk = 0; kk < 8; kk++) {
            float4 a0 = *(const float4*)&As[kk][ty * 4];
            float4 a1 = *(const float4*)&As[kk][64 + ty * 4];
            ulonglong2 b0 = *(const ulonglong2*)&Ws[kk][tx * 4];
            ulonglong2 b1 = *(const ulonglong2*)&Ws[kk][64 + tx * 4];
            float a[8] = {a0.x, a0.y, a0.z, a0.w, a1.x, a1.y, a1.z, a1.w};
            ull bv[4] = {b0.x, b0.y, b1.x, b1.y};
#pragma unroll
            for (int i = 0; i < 8; i++) {
                ull a2 = pk2(a[i], a[i]);
#pragma unroll
                for (int j = 0; j < 4; j++) acc[i][j] = ffma2(a2, bv[j], acc[i][j]);
            }
        }
    }

    float4 bias0 = *(const float4*)&bias[n0 + tx * 4];
    float4 bias1 = *(const float4*)&bias[n0 + 64 + tx * 4];

#pragma unroll
    for (int i = 0; i < 8; i++) {
        int m = m0 + (i >> 2) * 64 + ty * 4 + (i & 3);
        float4 r0, r1;
        upk2(acc[i][0], r0.x, r0.y); upk2(acc[i][1], r0.z, r0.w);
        upk2(acc[i][2], r1.x, r1.y); upk2(acc[i][3], r1.z, r1.w);
        r0.x += bias0.x; r0.y += bias0.y; r0.z += bias0.z; r0.w += bias0.w;
        r1.x += bias1.x; r1.y += bias1.y; r1.z += bias1.z; r1.w += bias1.w;
        if (MODE == 0) {
            int bb = m >> 11, ss = m & 2047;
            int nA = n0 + tx * 4;
            int nB = n0 + 64 + tx * 4;
            int hA = nA >> 6, dA = nA & 63;
            int hB = nB >> 6, dB = nB & 63;
            *(float4*)&out[((size_t)(bb * H + hA) * S + ss) * D + dA] = r0;
            *(float4*)&out[((size_t)(bb * H + hB) * S + ss) * D + dB] = r1;
        } else {
            *(float4*)&out[(size_t)m * 1024 + n0 + tx * 4] = r0;
            *(float4*)&out[(size_t)m * 1024 + n0 + 64 + tx * 4] = r1;
        }
    }
}

// fused Q/K/V projection: blockIdx.z selects input/weight/bias/output
__global__ __launch_bounds__(256) void gemm_proj(const float* __restrict__ xq,
                                                 const float* __restrict__ xk,
                                                 const float* __restrict__ xv,
                                                 const float* __restrict__ Wq,
                                                 const float* __restrict__ Wk,
                                                 const float* __restrict__ Wv,
                                                 const float* __restrict__ bq,
                                                 const float* __restrict__ bk,
                                                 const float* __restrict__ bv,
                                                 float* __restrict__ oq,
                                                 float* __restrict__ ok,
                                                 float* __restrict__ ov)
{
    const int z = blockIdx.z;
    const float* X = (z == 0) ? xq : (z == 1) ? xk : xv;
    const float* W = (z == 0) ? Wq : (z == 1) ? Wk : Wv;
    const float* bb = (z == 0) ? bq : (z == 1) ? bk : bv;
    float* out = (z == 0) ? oq : (z == 1) ? ok : ov;
    gemm_body<0>(X, W, bb, out);
}

__global__ __launch_bounds__(256) void gemm_out(const float* __restrict__ X,
                                                const float* __restrict__ W,
                                                const float* __restrict__ bias,
                                                float* __restrict__ out)
{
    gemm_body<1>(X, W, bias, out);
}

// ---------------------------------------------------------------------------
// flash attention, SIMT f32x2, group-wise online softmax (16 keys/group).
// One thread per Q row; K tile transposed [d][68]; Q stride 65 (conflict-free).
// ---------------------------------------------------------------------------
constexpr int BQ = 128, TK = 64;
constexpr int QSTR = 65, KSTR = 68;
constexpr int ATTN_SMEM = (BQ * QSTR + D * KSTR + TK * D) * 4;  // 67072

__global__ __launch_bounds__(128) void attn_kernel(const float* __restrict__ Q,
                                                   const float* __restrict__ K,
                                                   const float* __restrict__ V,
                                                   float* __restrict__ Oout)
{
    extern __shared__ float sm[];
    float* Qs  = sm;                  // [128][65]
    float* Kst = sm + BQ * QSTR;      // [64 d][68 keys]
    float* Vs  = Kst + D * KSTR;      // [64 keys][64 d]

    const int t  = threadIdx.x;
    const int bh = blockIdx.y;
    const int q0 = blockIdx.x * BQ;
    const float* Qb = Q + (size_t)bh * (S * D);
    const float* Kb = K + (size_t)bh * (S * D);
    const float* Vb = V + (size_t)bh * (S * D);

#pragma unroll
    for (int i = 0; i < BQ * D / 128; i++) {
        int idx = i * 128 + t;
        int r = idx >> 6, d = idx & 63;
        Qs[r * QSTR + d] = Qb[(q0 + r) * D + d] * 0.125f;
    }

    ull o2[32];
#pragma unroll
    for (int i = 0; i < 32; i++) o2[i] = 0ull;
    float m_run = -3.0e38f, l_run = 0.0f;

    for (int kt = 0; kt < S; kt += TK) {
        __syncthreads();
#pragma unroll
        for (int i = 0; i < TK * D / 128; i++) {
            int idx = i * 128 + t;
            int j = idx >> 6, d = idx & 63;
            Kst[d * KSTR + j] = Kb[(kt + j) * D + d];
            Vs[j * D + d]     = Vb[(kt + j) * D + d];
        }
        __syncthreads();

#pragma unroll
        for (int g = 0; g < 4; g++) {
            ull s2[8];
#pragma unroll
            for (int i = 0; i < 8; i++) s2[i] = 0ull;

#pragma unroll
            for (int dc = 0; dc < D; dc += 16) {
                float qf[16];
#pragma unroll
                for (int u = 0; u < 16; u++) qf[u] = Qs[t * QSTR + dc + u];
#pragma unroll
                for (int dd = 0; dd < 16; dd++) {
                    ull q2 = pk2(qf[dd], qf[dd]);
                    const ulonglong2* kr = (const ulonglong2*)&Kst[(dc + dd) * KSTR];
#pragma unroll
                    for (int u = 0; u < 4; u++) {
                        ulonglong2 kv = kr[g * 4 + u];
                        s2[2 * u]     = ffma2(q2, kv.x, s2[2 * u]);
                        s2[2 * u + 1] = ffma2(q2, kv.y, s2[2 * u + 1]);
                    }
                }
            }

            float gmax = -3.0e38f;
#pragma unroll
            for (int i = 0; i < 8; i++) {
                float a, b2; upk2(s2[i], a, b2);
                gmax = fmaxf(gmax, fmaxf(a, b2));
            }
            if (__any_sync(0xffffffffu, gmax > m_run)) {
                float mnew = fmaxf(m_run, gmax);
                float alpha = __expf(m_run - mnew);
                l_run *= alpha;
                ull al2 = pk2(alpha, alpha);
#pragma unroll
                for (int i = 0; i < 32; i++) o2[i] = fmul2(o2[i], al2);
                m_run = mnew;
            }
            float lsum = 0.0f;
#pragma unroll
            for (int i = 0; i < 8; i++) {
                float a, b2; upk2(s2[i], a, b2);
                float p0 = __expf(a - m_run);
                float p1 = __expf(b2 - m_run);
                lsum += p0 + p1;
                s2[i] = pk2(p0, p1);
            }
            l_run += lsum;

#pragma unroll
            for (int j2 = 0; j2 < 8; j2++) {
                int j = g * 16 + 2 * j2;
                float p0, p1; upk2(s2[j2], p0, p1);
                ull pa = pk2(p0, p0), pb = pk2(p1, p1);
                const ulonglong2* v0 = (const ulonglong2*)&Vs[j * D];
                const ulonglong2* v1 = (const ulonglong2*)&Vs[(j + 1) * D];
#pragma unroll
                for (int cp = 0; cp < 16; cp++) {
                    ulonglong2 va = v0[cp];
                    ulonglong2 vb = v1[cp];
                    o2[2 * cp]     = ffma2(pa, va.x, o2[2 * cp]);
                    o2[2 * cp + 1] = ffma2(pa, va.y, o2[2 * cp + 1]);
                    o2[2 * cp]     = ffma2(pb, vb.x, o2[2 * cp]);
                    o2[2 * cp + 1] = ffma2(pb, vb.y, o2[2 * cp + 1]);
                }
            }
        }
    }

    float inv_l = 1.0f / l_run;
    int bb = bh >> 4, hh = bh & 15;
    float* dst = Oout + (size_t)(bb * S + q0 + t) * E + hh * D;
#pragma unroll
    for (int cp = 0; cp < 16; cp++) {
        float x0, x1, x2, x3;
        upk2(o2[2 * cp], x0, x1);
        upk2(o2[2 * cp + 1], x2, x3);
        float4 o4 = { x0 * inv_l, x1 * inv_l, x2 * inv_l, x3 * inv_l };
        *(float4*)&dst[cp * 4] = o4;
    }
}

// ---------------------------------------------------------------------------
extern "C" void kernel_launch(void* const* d_in, const int* in_sizes, int n_in,
                              void* d_out, int out_size)
{
    const float* query = (const float*)d_in[0];
    const float* key   = (const float*)d_in[1];
    const float* value = (const float*)d_in[2];
    const float* Wq    = (const float*)d_in[3];
    const float* bq    = (const float*)d_in[4];
    const float* Wk    = (const float*)d_in[5];
    const float* bk    = (const float*)d_in[6];
    const float* Wv    = (const float*)d_in[7];
    const float* bv    = (const float*)d_in[8];
    const float* Wo    = (const float*)d_in[9];
    const float* bo    = (const float*)d_in[10];

    void *pq, *pk, *pv, *patt;
    cudaGetSymbolAddress(&pq, g_q);
    cudaGetSymbolAddress(&pk, g_k);
    cudaGetSymbolAddress(&pv, g_v);
    cudaGetSymbolAddress(&patt, g_att);

    cudaFuncSetAttribute(attn_kernel, cudaFuncAttributeMaxDynamicSharedMemorySize,
                         ATTN_SMEM);

    dim3 pgrid(8, 32, 3);
    gemm_proj<<<pgrid, 256>>>(query, key, value, Wq, Wk, Wv, bq, bk, bv,
                              (float*)pq, (float*)pk, (float*)pv);

    dim3 agrid(S / BQ, B * H);
    attn_kernel<<<agrid, 128, ATTN_SMEM>>>((const float*)pq, (const float*)pk,
                                           (const float*)pv, (float*)patt);

    dim3 ggrid(8, 32);
    gemm_out<<<ggrid, 256>>>((const float*)patt, Wo, bo, (float*)d_out);
}